// round 10
// baseline (speedup 1.0000x reference)
#include <cuda_runtime.h>

// CapsuleLayer dynamic routing, fully fused. Round 10: R6 base (98.8us) +
// deferred-Z softmax (Z off critical path) + pipelined cp.async W staging.
// (R9's redux.f32 removed: not supported on sm_103 — integer-only redux.)
// Shapes: B=64, R=2048, C=16, O=32, I=16. 3 routing iterations.
// Grid: (2048, 2). CTA = 256 threads = 8 warps, owns 32 b's; warp owns 4 b's
// as 2 f32x2 b-pairs, routing chains instruction-interleaved.

#define FULLM 0xffffffffu

static __device__ __forceinline__ float2 ffma2(float2 a, float2 b, float2 c) {
    unsigned long long ua = *reinterpret_cast<unsigned long long*>(&a);
    unsigned long long ub = *reinterpret_cast<unsigned long long*>(&b);
    unsigned long long uc = *reinterpret_cast<unsigned long long*>(&c);
    unsigned long long ud;
    asm("fma.rn.f32x2 %0, %1, %2, %3;" : "=l"(ud) : "l"(ua), "l"(ub), "l"(uc));
    return *reinterpret_cast<float2*>(&ud);
}
static __device__ __forceinline__ float2 add2(float2 a, float2 b) {
    unsigned long long ua = *reinterpret_cast<unsigned long long*>(&a);
    unsigned long long ub = *reinterpret_cast<unsigned long long*>(&b);
    unsigned long long ud;
    asm("add.rn.f32x2 %0, %1, %2;" : "=l"(ud) : "l"(ua), "l"(ub));
    return *reinterpret_cast<float2*>(&ud);
}
static __device__ __forceinline__ float2 mul2(float2 a, float2 b) {
    unsigned long long ua = *reinterpret_cast<unsigned long long*>(&a);
    unsigned long long ub = *reinterpret_cast<unsigned long long*>(&b);
    unsigned long long ud;
    asm("mul.rn.f32x2 %0, %1, %2;" : "=l"(ud) : "l"(ua), "l"(ub));
    return *reinterpret_cast<float2*>(&ud);
}
static __device__ __forceinline__ float2 pack2(float x) {
    unsigned long long r;
    asm("mov.b64 %0, {%1, %1};" : "=l"(r) : "f"(x));
    return *reinterpret_cast<float2*>(&r);
}
static __device__ __forceinline__ float rcp_approx(float x) {
    float r; asm("rcp.approx.f32 %0, %1;" : "=f"(r) : "f"(x)); return r;
}
static __device__ __forceinline__ float sqrt_approx(float x) {
    float r; asm("sqrt.approx.f32 %0, %1;" : "=f"(r) : "f"(x)); return r;
}
static __device__ __forceinline__ float2 shfl_xor2(float2 v, int m) {
    v.x = __shfl_xor_sync(FULLM, v.x, m);
    v.y = __shfl_xor_sync(FULLM, v.y, m);
    return v;
}
static __device__ __forceinline__ void cp_async16(unsigned dst_smem, const void* src) {
    asm volatile("cp.async.ca.shared.global [%0], [%1], 16;" :: "r"(dst_smem), "l"(src));
}

// squash for BOTH pairs, interleaved shuffle trees: v = s*sqrt(n)/(1+n), n = sum_o s^2.
static __device__ __forceinline__ void squash_x2(float2& s0, float2& s1) {
    float2 n0 = mul2(s0, s0);
    float2 n1 = mul2(s1, s1);
#pragma unroll
    for (int m = 16; m >= 1; m >>= 1) {
        n0 = add2(n0, shfl_xor2(n0, m));
        n1 = add2(n1, shfl_xor2(n1, m));
    }
    float f0x = sqrt_approx(n0.x) * rcp_approx(1.0f + n0.x);
    float f0y = sqrt_approx(n0.y) * rcp_approx(1.0f + n0.y);
    float f1x = sqrt_approx(n1.x) * rcp_approx(1.0f + n1.x);
    float f1y = sqrt_approx(n1.y) * rcp_approx(1.0f + n1.y);
    s0 = mul2(s0, make_float2(f0x, f0y));
    s1 = mul2(s1, make_float2(f1x, f1y));
}

// Transpose-reduce for BOTH pairs, interleaved, register-streamed:
// r{q}[lane] = Sum_o S{q}[lane%16][o]*v{q}[o], replicated on both 16-lane halves.
static __device__ __forceinline__ void tr16_x2s(
    const float2* __restrict__ S0, const float2* __restrict__ S1,
    float2 v0, float2 v1, int lane, float2& r0, float2& r1)
{
    const int p0 = lane & 1, p1 = (lane >> 1) & 1, p2 = (lane >> 2) & 1, p3 = (lane >> 3) & 1;
    float2 c0[4], c1[4];
#pragma unroll
    for (int g = 0; g < 4; g++) {
        float2 a00, a01, a10, a11;
        {
            int k = 2 * g;
            float2 kA = mul2(p0 ? S0[2 * k + 1] : S0[2 * k], v0);
            float2 gA = mul2(p0 ? S0[2 * k] : S0[2 * k + 1], v0);
            float2 kB = mul2(p0 ? S1[2 * k + 1] : S1[2 * k], v1);
            float2 gB = mul2(p0 ? S1[2 * k] : S1[2 * k + 1], v1);
            a00 = add2(kA, shfl_xor2(gA, 1));
            a10 = add2(kB, shfl_xor2(gB, 1));
            k = 2 * g + 1;
            kA = mul2(p0 ? S0[2 * k + 1] : S0[2 * k], v0);
            gA = mul2(p0 ? S0[2 * k] : S0[2 * k + 1], v0);
            kB = mul2(p0 ? S1[2 * k + 1] : S1[2 * k], v1);
            gB = mul2(p0 ? S1[2 * k] : S1[2 * k + 1], v1);
            a01 = add2(kA, shfl_xor2(gA, 1));
            a11 = add2(kB, shfl_xor2(gB, 1));
        }
        float2 kA = p1 ? a01 : a00, gA = p1 ? a00 : a01;
        float2 kB = p1 ? a11 : a10, gB = p1 ? a10 : a11;
        c0[g] = add2(kA, shfl_xor2(gA, 2));
        c1[g] = add2(kB, shfl_xor2(gB, 2));
    }
    float2 d00, d01, d10, d11;
    {
        float2 kA = p2 ? c0[1] : c0[0], gA = p2 ? c0[0] : c0[1];
        float2 kB = p2 ? c1[1] : c1[0], gB = p2 ? c1[0] : c1[1];
        d00 = add2(kA, shfl_xor2(gA, 4));
        d10 = add2(kB, shfl_xor2(gB, 4));
        kA = p2 ? c0[3] : c0[2]; gA = p2 ? c0[2] : c0[3];
        kB = p2 ? c1[3] : c1[2]; gB = p2 ? c1[2] : c1[3];
        d01 = add2(kA, shfl_xor2(gA, 4));
        d11 = add2(kB, shfl_xor2(gB, 4));
    }
    float2 e0, e1;
    {
        float2 kA = p3 ? d01 : d00, gA = p3 ? d00 : d01;
        float2 kB = p3 ? d11 : d10, gB = p3 ? d10 : d11;
        e0 = add2(kA, shfl_xor2(gA, 8));
        e1 = add2(kB, shfl_xor2(gB, 8));
    }
    e0 = add2(e0, shfl_xor2(e0, 16));
    e1 = add2(e1, shfl_xor2(e1, 16));
    r0 = e0;
    r1 = e1;
}

// One i4-chunk of the u_hat GEMM (16 c x 2 b-pairs x 4 i-values).
static __device__ __forceinline__ void gemm_chunk(
    int i4, int wid, int lane,
    const float4* __restrict__ Ws4, const float2* __restrict__ Xs,
    float2 (&u)[2][16])
{
    float2 xv[2][4];
#pragma unroll
    for (int p = 0; p < 2; p++) {
        const float4* xp = reinterpret_cast<const float4*>(&Xs[(wid * 2 + p) * 16 + i4 * 4]);
        float4 q0 = xp[0];   // uniform (broadcast) LDS.128
        float4 q1 = xp[1];
        xv[p][0] = make_float2(q0.x, q0.y);
        xv[p][1] = make_float2(q0.z, q0.w);
        xv[p][2] = make_float2(q1.x, q1.y);
        xv[p][3] = make_float2(q1.z, q1.w);
    }
#pragma unroll
    for (int c = 0; c < 16; c++) {
        float4 w4 = Ws4[i4 * 514 + c * 32 + lane];
        float2 w0 = pack2(w4.x), w1 = pack2(w4.y), w2 = pack2(w4.z), w3 = pack2(w4.w);
#pragma unroll
        for (int p = 0; p < 2; p++) {
            u[p][c] = ffma2(w0, xv[p][0], u[p][c]);
            u[p][c] = ffma2(w1, xv[p][1], u[p][c]);
            u[p][c] = ffma2(w2, xv[p][2], u[p][c]);
            u[p][c] = ffma2(w3, xv[p][3], u[p][c]);
        }
    }
}

__global__ void __launch_bounds__(256, 2)
caps_routing_kernel(const float* __restrict__ x,   // [64, 2048, 16]
                    const float* __restrict__ W,   // [2048, 16, 32, 16]
                    float* __restrict__ out)       // [64, 2048, 32]
{
    const int r = blockIdx.x;
    const int b_base = blockIdx.y << 5;   // 0 or 32
    const int tid = threadIdx.x;
    const int lane = tid & 31;   // = o
    const int wid = tid >> 5;    // 0..7

    __shared__ float4 Ws4[4 * 514];          // [i4][c][o] float4, padded
    __shared__ float2 Xs[16 * 16];           // x b-pairs for this CTA's 32 b's
    __shared__ float2 Rbuf[8][2][16];        // per-warp, per-pair exp rows

    // ---- stage W[r] (32 KB), i4-major transpose, 4 cp.async commit groups ----
    {
        const float4* Wg4 = reinterpret_cast<const float4*>(W + (size_t)r * 8192);
        unsigned ws_base = (unsigned)__cvta_generic_to_shared(Ws4);
#pragma unroll
        for (int i4 = 0; i4 < 4; i4++) {
#pragma unroll
            for (int k = 0; k < 2; k++) {
                int m = tid + k * 256;       // m = c*32 + o
                int c = m >> 5, o = m & 31;
                cp_async16(ws_base + (unsigned)((i4 * 514 + c * 32 + o) * 16),
                           Wg4 + 4 * m + i4);
            }
            asm volatile("cp.async.commit_group;" ::: "memory");
        }
    }
    // ---- stage x[b_base : b_base+32, r, :] packed as b-pairs ----
    if (tid < 128) {
        int b_loc = tid >> 2, q = tid & 3;
        const float4* xg4 = reinterpret_cast<const float4*>(
            x + (size_t)(b_base + b_loc) * 32768 + (size_t)r * 16);
        float4 xv = xg4[q];
        int p = b_loc >> 1, par = b_loc & 1;
        float* xsf = reinterpret_cast<float*>(Xs);
        xsf[((p * 16 + q * 4 + 0) << 1) + par] = xv.x;
        xsf[((p * 16 + q * 4 + 1) << 1) + par] = xv.y;
        xsf[((p * 16 + q * 4 + 2) << 1) + par] = xv.z;
        xsf[((p * 16 + q * 4 + 3) << 1) + par] = xv.w;
    }

    // ---- u_hat, pipelined against staging: chunk k starts after group k lands ----
    float2 u[2][16];
#pragma unroll
    for (int p = 0; p < 2; p++)
#pragma unroll
        for (int c = 0; c < 16; c++) u[p][c] = make_float2(0.f, 0.f);

    asm volatile("cp.async.wait_group 3;" ::: "memory");
    __syncthreads();                 // x + W chunk 0 visible
    gemm_chunk(0, wid, lane, Ws4, Xs, u);
    asm volatile("cp.async.wait_group 2;" ::: "memory");
    __syncthreads();
    gemm_chunk(1, wid, lane, Ws4, Xs, u);
    asm volatile("cp.async.wait_group 1;" ::: "memory");
    __syncthreads();
    gemm_chunk(2, wid, lane, Ws4, Xs, u);
    asm volatile("cp.async.wait_group 0;" ::: "memory");
    __syncthreads();
    gemm_chunk(3, wid, lane, Ws4, Xs, u);

    // ---- routing: BOTH pairs interleaved. Iter1 softmax(0)=uniform; final b-update dead. ----
    const float2* S0 = u[0];
    const float2* S1 = u[1];

    // iteration 1: route = 1/16 uniform -> s = mean over c
    float2 s0, s1;
    {
        float2 t0[4], t1[4];
#pragma unroll
        for (int k = 0; k < 4; k++) {
            t0[k] = add2(add2(S0[4 * k], S0[4 * k + 1]), add2(S0[4 * k + 2], S0[4 * k + 3]));
            t1[k] = add2(add2(S1[4 * k], S1[4 * k + 1]), add2(S1[4 * k + 2], S1[4 * k + 3]));
        }
        s0 = add2(add2(t0[0], t0[1]), add2(t0[2], t0[3]));
        s1 = add2(add2(t1[0], t1[1]), add2(t1[2], t1[3]));
        const float2 k16 = make_float2(0.0625f, 0.0625f);
        s0 = mul2(s0, k16);
        s1 = mul2(s1, k16);
    }

    squash_x2(s0, s1);                 // s -> v (in place)
    float2 bown0, bown1;
    tr16_x2s(S0, S1, s0, s1, lane, bown0, bown1);

#pragma unroll
    for (int it = 0; it < 2; it++) {
        // Deferred-normalization softmax: broadcast UNNORMALIZED e; Z summed
        // from the same quads during s-accumulation (off the critical path).
        float2 e0 = make_float2(__expf(bown0.x), __expf(bown0.y));
        float2 e1 = make_float2(__expf(bown1.x), __expf(bown1.y));

        __syncwarp();
        if (lane < 16) {
            Rbuf[wid][0][lane] = e0;
            Rbuf[wid][1][lane] = e1;
        }
        __syncwarp();

        const float4* rb0 = reinterpret_cast<const float4*>(&Rbuf[wid][0][0]);
        const float4* rb1 = reinterpret_cast<const float4*>(&Rbuf[wid][1][0]);
        float2 sa0 = make_float2(0.f, 0.f), sb0 = make_float2(0.f, 0.f);
        float2 sa1 = make_float2(0.f, 0.f), sb1 = make_float2(0.f, 0.f);
        float2 Z0 = make_float2(0.f, 0.f), Z1 = make_float2(0.f, 0.f);
#pragma unroll
        for (int j = 0; j < 8; j++) {
            float4 t0 = rb0[j];
            float4 t1 = rb1[j];
            float2 ta0 = make_float2(t0.x, t0.y), tb0 = make_float2(t0.z, t0.w);
            float2 ta1 = make_float2(t1.x, t1.y), tb1 = make_float2(t1.z, t1.w);
            sa0 = ffma2(ta0, S0[2 * j + 0], sa0);
            sb0 = ffma2(tb0, S0[2 * j + 1], sb0);
            sa1 = ffma2(ta1, S1[2 * j + 0], sa1);
            sb1 = ffma2(tb1, S1[2 * j + 1], sb1);
            Z0 = add2(Z0, add2(ta0, tb0));
            Z1 = add2(Z1, add2(ta1, tb1));
        }
        float2 rz0 = make_float2(rcp_approx(Z0.x), rcp_approx(Z0.y));
        float2 rz1 = make_float2(rcp_approx(Z1.x), rcp_approx(Z1.y));
        s0 = mul2(add2(sa0, sb0), rz0);
        s1 = mul2(add2(sa1, sb1), rz1);

        squash_x2(s0, s1);             // s -> v

        if (it == 0) {
            float2 d0, d1;
            tr16_x2s(S0, S1, s0, s1, lane, d0, d1);
            bown0 = add2(bown0, d0);
            bown1 = add2(bown1, d1);
        }
    }

    // ---- write v for all 4 b's: out[b][r][o] ----
    {
        const int bg = b_base + wid * 4;
        float* o0 = out + (size_t)bg * 65536 + (size_t)r * 32 + lane;
        o0[0 * 65536] = s0.x;
        o0[1 * 65536] = s0.y;
        o0[2 * 65536] = s1.x;
        o0[3 * 65536] = s1.y;
    }
}

extern "C" void kernel_launch(void* const* d_in, const int* in_sizes, int n_in,
                              void* d_out, int out_size) {
    const float* x = (const float*)d_in[0];
    const float* W = (const float*)d_in[1];
    // defensive: x is the smaller input (2,097,152 vs 16,777,216 elements)
    if (n_in >= 2 && in_sizes[0] > in_sizes[1]) {
        const float* t = x; x = W; W = t;
    }
    float* out = (float*)d_out;
    dim3 grid(2048, 2);
    caps_routing_kernel<<<grid, 256>>>(x, W, out);
}

// round 11
// speedup vs baseline: 1.0967x; 1.0967x over previous
#include <cuda_runtime.h>

// CapsuleLayer dynamic routing, fully fused. Round 11: R6 staging (contiguous
// monolithic cp.async, 98.8us baseline) + deferred-Z softmax only.
// R10's per-chunk staging reverted: its strided cp.async gather + 4 extra
// __syncthreads cost 12us.
// Shapes: B=64, R=2048, C=16, O=32, I=16. 3 routing iterations.
// Grid: (2048, 2). CTA = 256 threads = 8 warps, owns 32 b's; warp owns 4 b's
// as 2 f32x2 b-pairs, routing chains instruction-interleaved.

#define FULLM 0xffffffffu

static __device__ __forceinline__ float2 ffma2(float2 a, float2 b, float2 c) {
    unsigned long long ua = *reinterpret_cast<unsigned long long*>(&a);
    unsigned long long ub = *reinterpret_cast<unsigned long long*>(&b);
    unsigned long long uc = *reinterpret_cast<unsigned long long*>(&c);
    unsigned long long ud;
    asm("fma.rn.f32x2 %0, %1, %2, %3;" : "=l"(ud) : "l"(ua), "l"(ub), "l"(uc));
    return *reinterpret_cast<float2*>(&ud);
}
static __device__ __forceinline__ float2 add2(float2 a, float2 b) {
    unsigned long long ua = *reinterpret_cast<unsigned long long*>(&a);
    unsigned long long ub = *reinterpret_cast<unsigned long long*>(&b);
    unsigned long long ud;
    asm("add.rn.f32x2 %0, %1, %2;" : "=l"(ud) : "l"(ua), "l"(ub));
    return *reinterpret_cast<float2*>(&ud);
}
static __device__ __forceinline__ float2 mul2(float2 a, float2 b) {
    unsigned long long ua = *reinterpret_cast<unsigned long long*>(&a);
    unsigned long long ub = *reinterpret_cast<unsigned long long*>(&b);
    unsigned long long ud;
    asm("mul.rn.f32x2 %0, %1, %2;" : "=l"(ud) : "l"(ua), "l"(ub));
    return *reinterpret_cast<float2*>(&ud);
}
static __device__ __forceinline__ float2 pack2(float x) {
    unsigned long long r;
    asm("mov.b64 %0, {%1, %1};" : "=l"(r) : "f"(x));
    return *reinterpret_cast<float2*>(&r);
}
static __device__ __forceinline__ float rcp_approx(float x) {
    float r; asm("rcp.approx.f32 %0, %1;" : "=f"(r) : "f"(x)); return r;
}
static __device__ __forceinline__ float sqrt_approx(float x) {
    float r; asm("sqrt.approx.f32 %0, %1;" : "=f"(r) : "f"(x)); return r;
}
static __device__ __forceinline__ float2 shfl_xor2(float2 v, int m) {
    v.x = __shfl_xor_sync(FULLM, v.x, m);
    v.y = __shfl_xor_sync(FULLM, v.y, m);
    return v;
}
static __device__ __forceinline__ void cp_async16(unsigned dst_smem, const void* src) {
    asm volatile("cp.async.ca.shared.global [%0], [%1], 16;" :: "r"(dst_smem), "l"(src));
}

// squash for BOTH pairs, interleaved shuffle trees: v = s*sqrt(n)/(1+n), n = sum_o s^2.
static __device__ __forceinline__ void squash_x2(float2& s0, float2& s1) {
    float2 n0 = mul2(s0, s0);
    float2 n1 = mul2(s1, s1);
#pragma unroll
    for (int m = 16; m >= 1; m >>= 1) {
        n0 = add2(n0, shfl_xor2(n0, m));
        n1 = add2(n1, shfl_xor2(n1, m));
    }
    float f0x = sqrt_approx(n0.x) * rcp_approx(1.0f + n0.x);
    float f0y = sqrt_approx(n0.y) * rcp_approx(1.0f + n0.y);
    float f1x = sqrt_approx(n1.x) * rcp_approx(1.0f + n1.x);
    float f1y = sqrt_approx(n1.y) * rcp_approx(1.0f + n1.y);
    s0 = mul2(s0, make_float2(f0x, f0y));
    s1 = mul2(s1, make_float2(f1x, f1y));
}

// Transpose-reduce for BOTH pairs, interleaved, register-streamed:
// r{q}[lane] = Sum_o S{q}[lane%16][o]*v{q}[o], replicated on both 16-lane halves.
static __device__ __forceinline__ void tr16_x2s(
    const float2* __restrict__ S0, const float2* __restrict__ S1,
    float2 v0, float2 v1, int lane, float2& r0, float2& r1)
{
    const int p0 = lane & 1, p1 = (lane >> 1) & 1, p2 = (lane >> 2) & 1, p3 = (lane >> 3) & 1;
    float2 c0[4], c1[4];
#pragma unroll
    for (int g = 0; g < 4; g++) {
        float2 a00, a01, a10, a11;
        {
            int k = 2 * g;
            float2 kA = mul2(p0 ? S0[2 * k + 1] : S0[2 * k], v0);
            float2 gA = mul2(p0 ? S0[2 * k] : S0[2 * k + 1], v0);
            float2 kB = mul2(p0 ? S1[2 * k + 1] : S1[2 * k], v1);
            float2 gB = mul2(p0 ? S1[2 * k] : S1[2 * k + 1], v1);
            a00 = add2(kA, shfl_xor2(gA, 1));
            a10 = add2(kB, shfl_xor2(gB, 1));
            k = 2 * g + 1;
            kA = mul2(p0 ? S0[2 * k + 1] : S0[2 * k], v0);
            gA = mul2(p0 ? S0[2 * k] : S0[2 * k + 1], v0);
            kB = mul2(p0 ? S1[2 * k + 1] : S1[2 * k], v1);
            gB = mul2(p0 ? S1[2 * k] : S1[2 * k + 1], v1);
            a01 = add2(kA, shfl_xor2(gA, 1));
            a11 = add2(kB, shfl_xor2(gB, 1));
        }
        float2 kA = p1 ? a01 : a00, gA = p1 ? a00 : a01;
        float2 kB = p1 ? a11 : a10, gB = p1 ? a10 : a11;
        c0[g] = add2(kA, shfl_xor2(gA, 2));
        c1[g] = add2(kB, shfl_xor2(gB, 2));
    }
    float2 d00, d01, d10, d11;
    {
        float2 kA = p2 ? c0[1] : c0[0], gA = p2 ? c0[0] : c0[1];
        float2 kB = p2 ? c1[1] : c1[0], gB = p2 ? c1[0] : c1[1];
        d00 = add2(kA, shfl_xor2(gA, 4));
        d10 = add2(kB, shfl_xor2(gB, 4));
        kA = p2 ? c0[3] : c0[2]; gA = p2 ? c0[2] : c0[3];
        kB = p2 ? c1[3] : c1[2]; gB = p2 ? c1[2] : c1[3];
        d01 = add2(kA, shfl_xor2(gA, 4));
        d11 = add2(kB, shfl_xor2(gB, 4));
    }
    float2 e0, e1;
    {
        float2 kA = p3 ? d01 : d00, gA = p3 ? d00 : d01;
        float2 kB = p3 ? d11 : d10, gB = p3 ? d10 : d11;
        e0 = add2(kA, shfl_xor2(gA, 8));
        e1 = add2(kB, shfl_xor2(gB, 8));
    }
    e0 = add2(e0, shfl_xor2(e0, 16));
    e1 = add2(e1, shfl_xor2(e1, 16));
    r0 = e0;
    r1 = e1;
}

__global__ void __launch_bounds__(256, 2)
caps_routing_kernel(const float* __restrict__ x,   // [64, 2048, 16]
                    const float* __restrict__ W,   // [2048, 16, 32, 16]
                    float* __restrict__ out)       // [64, 2048, 32]
{
    const int r = blockIdx.x;
    const int b_base = blockIdx.y << 5;   // 0 or 32
    const int tid = threadIdx.x;
    const int lane = tid & 31;   // = o
    const int wid = tid >> 5;    // 0..7

    __shared__ float4 Ws4[4 * 514];          // [i4][c][o] float4, padded
    __shared__ float2 Xs[16 * 16];           // x b-pairs for this CTA's 32 b's
    __shared__ float2 Rbuf[8][2][16];        // per-warp, per-pair exp rows

    // ---- stage W[r] (32 KB) with i4-major transpose via cp.async (contiguous src) ----
    {
        const float4* Wg4 = reinterpret_cast<const float4*>(W + (size_t)r * 8192);
        unsigned ws_base = (unsigned)__cvta_generic_to_shared(Ws4);
#pragma unroll
        for (int k = 0; k < 8; k++) {
            int f = tid + k * 256;           // float4 index within [16c][32o][4 i4]
            int c = f >> 7, o = (f >> 2) & 31, i4 = f & 3;
            cp_async16(ws_base + (unsigned)((i4 * 514 + c * 32 + o) * 16), Wg4 + f);
        }
        asm volatile("cp.async.commit_group;" ::: "memory");
    }
    // ---- stage x[b_base : b_base+32, r, :] packed as b-pairs ----
    if (tid < 128) {
        int b_loc = tid >> 2, q = tid & 3;
        const float4* xg4 = reinterpret_cast<const float4*>(
            x + (size_t)(b_base + b_loc) * 32768 + (size_t)r * 16);
        float4 xv = xg4[q];
        int p = b_loc >> 1, par = b_loc & 1;
        float* xsf = reinterpret_cast<float*>(Xs);
        xsf[((p * 16 + q * 4 + 0) << 1) + par] = xv.x;
        xsf[((p * 16 + q * 4 + 1) << 1) + par] = xv.y;
        xsf[((p * 16 + q * 4 + 2) << 1) + par] = xv.z;
        xsf[((p * 16 + q * 4 + 3) << 1) + par] = xv.w;
    }
    asm volatile("cp.async.wait_group 0;" ::: "memory");
    __syncthreads();

    // ---- u_hat: u[p][c] = f32x2 over local b-pair (wid*2+p), lane = o ----
    float2 u[2][16];
#pragma unroll
    for (int p = 0; p < 2; p++)
#pragma unroll
        for (int c = 0; c < 16; c++) u[p][c] = make_float2(0.f, 0.f);

#pragma unroll
    for (int i4 = 0; i4 < 4; i4++) {
        float2 xv[2][4];
#pragma unroll
        for (int p = 0; p < 2; p++) {
            const float4* xp = reinterpret_cast<const float4*>(&Xs[(wid * 2 + p) * 16 + i4 * 4]);
            float4 q0 = xp[0];   // uniform (broadcast) LDS.128
            float4 q1 = xp[1];
            xv[p][0] = make_float2(q0.x, q0.y);
            xv[p][1] = make_float2(q0.z, q0.w);
            xv[p][2] = make_float2(q1.x, q1.y);
            xv[p][3] = make_float2(q1.z, q1.w);
        }
#pragma unroll
        for (int c = 0; c < 16; c++) {
            float4 w4 = Ws4[i4 * 514 + c * 32 + lane];
            float2 w0 = pack2(w4.x), w1 = pack2(w4.y), w2 = pack2(w4.z), w3 = pack2(w4.w);
#pragma unroll
            for (int p = 0; p < 2; p++) {
                u[p][c] = ffma2(w0, xv[p][0], u[p][c]);
                u[p][c] = ffma2(w1, xv[p][1], u[p][c]);
                u[p][c] = ffma2(w2, xv[p][2], u[p][c]);
                u[p][c] = ffma2(w3, xv[p][3], u[p][c]);
            }
        }
    }

    // ---- routing: BOTH pairs interleaved. Iter1 softmax(0)=uniform; final b-update dead. ----
    const float2* S0 = u[0];
    const float2* S1 = u[1];

    // iteration 1: route = 1/16 uniform -> s = mean over c
    float2 s0, s1;
    {
        float2 t0[4], t1[4];
#pragma unroll
        for (int k = 0; k < 4; k++) {
            t0[k] = add2(add2(S0[4 * k], S0[4 * k + 1]), add2(S0[4 * k + 2], S0[4 * k + 3]));
            t1[k] = add2(add2(S1[4 * k], S1[4 * k + 1]), add2(S1[4 * k + 2], S1[4 * k + 3]));
        }
        s0 = add2(add2(t0[0], t0[1]), add2(t0[2], t0[3]));
        s1 = add2(add2(t1[0], t1[1]), add2(t1[2], t1[3]));
        const float2 k16 = make_float2(0.0625f, 0.0625f);
        s0 = mul2(s0, k16);
        s1 = mul2(s1, k16);
    }

    squash_x2(s0, s1);                 // s -> v (in place)
    float2 bown0, bown1;
    tr16_x2s(S0, S1, s0, s1, lane, bown0, bown1);

#pragma unroll
    for (int it = 0; it < 2; it++) {
        // Deferred-normalization softmax: broadcast UNNORMALIZED e; Z summed
        // from the same quads during s-accumulation (off the critical path).
        float2 e0 = make_float2(__expf(bown0.x), __expf(bown0.y));
        float2 e1 = make_float2(__expf(bown1.x), __expf(bown1.y));

        __syncwarp();
        if (lane < 16) {
            Rbuf[wid][0][lane] = e0;
            Rbuf[wid][1][lane] = e1;
        }
        __syncwarp();

        const float4* rb0 = reinterpret_cast<const float4*>(&Rbuf[wid][0][0]);
        const float4* rb1 = reinterpret_cast<const float4*>(&Rbuf[wid][1][0]);
        float2 sa0 = make_float2(0.f, 0.f), sb0 = make_float2(0.f, 0.f);
        float2 sa1 = make_float2(0.f, 0.f), sb1 = make_float2(0.f, 0.f);
        float2 Z0 = make_float2(0.f, 0.f), Z1 = make_float2(0.f, 0.f);
#pragma unroll
        for (int j = 0; j < 8; j++) {
            float4 t0 = rb0[j];
            float4 t1 = rb1[j];
            float2 ta0 = make_float2(t0.x, t0.y), tb0 = make_float2(t0.z, t0.w);
            float2 ta1 = make_float2(t1.x, t1.y), tb1 = make_float2(t1.z, t1.w);
            sa0 = ffma2(ta0, S0[2 * j + 0], sa0);
            sb0 = ffma2(tb0, S0[2 * j + 1], sb0);
            sa1 = ffma2(ta1, S1[2 * j + 0], sa1);
            sb1 = ffma2(tb1, S1[2 * j + 1], sb1);
            Z0 = add2(Z0, add2(ta0, tb0));
            Z1 = add2(Z1, add2(ta1, tb1));
        }
        float2 rz0 = make_float2(rcp_approx(Z0.x), rcp_approx(Z0.y));
        float2 rz1 = make_float2(rcp_approx(Z1.x), rcp_approx(Z1.y));
        s0 = mul2(add2(sa0, sb0), rz0);
        s1 = mul2(add2(sa1, sb1), rz1);

        squash_x2(s0, s1);             // s -> v

        if (it == 0) {
            float2 d0, d1;
            tr16_x2s(S0, S1, s0, s1, lane, d0, d1);
            bown0 = add2(bown0, d0);
            bown1 = add2(bown1, d1);
        }
    }

    // ---- write v for all 4 b's: out[b][r][o] ----
    {
        const int bg = b_base + wid * 4;
        float* o0 = out + (size_t)bg * 65536 + (size_t)r * 32 + lane;
        o0[0 * 65536] = s0.x;
        o0[1 * 65536] = s0.y;
        o0[2 * 65536] = s1.x;
        o0[3 * 65536] = s1.y;
    }
}

extern "C" void kernel_launch(void* const* d_in, const int* in_sizes, int n_in,
                              void* d_out, int out_size) {
    const float* x = (const float*)d_in[0];
    const float* W = (const float*)d_in[1];
    // defensive: x is the smaller input (2,097,152 vs 16,777,216 elements)
    if (n_in >= 2 && in_sizes[0] > in_sizes[1]) {
        const float* t = x; x = W; W = t;
    }
    float* out = (float*)d_out;
    dim3 grid(2048, 2);
    caps_routing_kernel<<<grid, 256>>>(x, W, out);
}

// round 12
// speedup vs baseline: 1.1068x; 1.0092x over previous
#include <cuda_runtime.h>

// CapsuleLayer dynamic routing, fully fused. Round 12: o-pair lane layout.
// lane = (b-half, o-pair): half-warp owns one b; f32x2 spans o-pairs.
// -> zero pack-MOVs in GEMM, 4-level (16-lane) reduction trees in routing,
//    free 2x b-parallelism across half-warps, deferred-Z softmax.
// Shapes: B=64, R=2048, C=16, O=32, I=16. 3 routing iterations.
// Grid: (2048, 2). CTA = 256 threads = 8 warps, owns 32 b's; warp owns 4 b's
// as 2 g-groups x 2 half-warps.

#define FULLM 0xffffffffu

static __device__ __forceinline__ float2 ffma2(float2 a, float2 b, float2 c) {
    unsigned long long ua = *reinterpret_cast<unsigned long long*>(&a);
    unsigned long long ub = *reinterpret_cast<unsigned long long*>(&b);
    unsigned long long uc = *reinterpret_cast<unsigned long long*>(&c);
    unsigned long long ud;
    asm("fma.rn.f32x2 %0, %1, %2, %3;" : "=l"(ud) : "l"(ua), "l"(ub), "l"(uc));
    return *reinterpret_cast<float2*>(&ud);
}
static __device__ __forceinline__ float2 add2(float2 a, float2 b) {
    unsigned long long ua = *reinterpret_cast<unsigned long long*>(&a);
    unsigned long long ub = *reinterpret_cast<unsigned long long*>(&b);
    unsigned long long ud;
    asm("add.rn.f32x2 %0, %1, %2;" : "=l"(ud) : "l"(ua), "l"(ub));
    return *reinterpret_cast<float2*>(&ud);
}
static __device__ __forceinline__ float2 mul2(float2 a, float2 b) {
    unsigned long long ua = *reinterpret_cast<unsigned long long*>(&a);
    unsigned long long ub = *reinterpret_cast<unsigned long long*>(&b);
    unsigned long long ud;
    asm("mul.rn.f32x2 %0, %1, %2;" : "=l"(ud) : "l"(ua), "l"(ub));
    return *reinterpret_cast<float2*>(&ud);
}
static __device__ __forceinline__ float2 pack2(float x) {
    unsigned long long r;
    asm("mov.b64 %0, {%1, %1};" : "=l"(r) : "f"(x));
    return *reinterpret_cast<float2*>(&r);
}
static __device__ __forceinline__ float rcp_approx(float x) {
    float r; asm("rcp.approx.f32 %0, %1;" : "=f"(r) : "f"(x)); return r;
}
static __device__ __forceinline__ float sqrt_approx(float x) {
    float r; asm("sqrt.approx.f32 %0, %1;" : "=f"(r) : "f"(x)); return r;
}

// squash for both g-chains (each half-warp = its own b). 4-level 16-lane trees.
// n = sum over all 32 o of s^2 (16 lanes x f32x2 horizontal).
static __device__ __forceinline__ void squash_g2(float2& s0, float2& s1) {
    float h0 = fmaf(s0.x, s0.x, s0.y * s0.y);
    float h1 = fmaf(s1.x, s1.x, s1.y * s1.y);
#pragma unroll
    for (int m = 1; m <= 8; m <<= 1) {
        h0 += __shfl_xor_sync(FULLM, h0, m);
        h1 += __shfl_xor_sync(FULLM, h1, m);
    }
    float f0 = sqrt_approx(h0) * rcp_approx(1.0f + h0);
    float f1 = sqrt_approx(h1) * rcp_approx(1.0f + h1);
    s0 = mul2(s0, pack2(f0));
    s1 = mul2(s1, pack2(f1));
}

// Transpose-reduce, both g-chains interleaved, streamed (bounded live regs).
// Per half-warp: bown[c=op] = Sum_o u[c][o]*v[o]. 4-level 16-lane butterfly.
static __device__ __forceinline__ void tr16_g2(
    const float2* __restrict__ U0, const float2* __restrict__ U1,
    float2 v0, float2 v1, int op, float& r0, float& r1)
{
    const int q0 = op & 1, q1 = (op >> 1) & 1, q2 = (op >> 2) & 1, q3 = (op >> 3) & 1;
    float a0[8], a1[8];
#pragma unroll
    for (int k = 0; k < 8; k++) {
        float2 m0e = mul2(U0[2 * k], v0);
        float2 m0o = mul2(U0[2 * k + 1], v0);
        float2 m1e = mul2(U1[2 * k], v1);
        float2 m1o = mul2(U1[2 * k + 1], v1);
        float t0e = m0e.x + m0e.y, t0o = m0o.x + m0o.y;
        float t1e = m1e.x + m1e.y, t1o = m1o.x + m1o.y;
        float k0 = q0 ? t0o : t0e, g0 = q0 ? t0e : t0o;
        float k1 = q0 ? t1o : t1e, g1 = q0 ? t1e : t1o;
        a0[k] = k0 + __shfl_xor_sync(FULLM, g0, 1);
        a1[k] = k1 + __shfl_xor_sync(FULLM, g1, 1);
    }
    float c0[4], c1[4];
#pragma unroll
    for (int k = 0; k < 4; k++) {
        float k0 = q1 ? a0[2 * k + 1] : a0[2 * k], g0 = q1 ? a0[2 * k] : a0[2 * k + 1];
        float k1 = q1 ? a1[2 * k + 1] : a1[2 * k], g1 = q1 ? a1[2 * k] : a1[2 * k + 1];
        c0[k] = k0 + __shfl_xor_sync(FULLM, g0, 2);
        c1[k] = k1 + __shfl_xor_sync(FULLM, g1, 2);
    }
    float d00, d01, d10, d11;
    {
        float k0 = q2 ? c0[1] : c0[0], g0 = q2 ? c0[0] : c0[1];
        float k1 = q2 ? c1[1] : c1[0], g1 = q2 ? c1[0] : c1[1];
        d00 = k0 + __shfl_xor_sync(FULLM, g0, 4);
        d10 = k1 + __shfl_xor_sync(FULLM, g1, 4);
        k0 = q2 ? c0[3] : c0[2]; g0 = q2 ? c0[2] : c0[3];
        k1 = q2 ? c1[3] : c1[2]; g1 = q2 ? c1[2] : c1[3];
        d01 = k0 + __shfl_xor_sync(FULLM, g0, 4);
        d11 = k1 + __shfl_xor_sync(FULLM, g1, 4);
    }
    {
        float k0 = q3 ? d01 : d00, g0 = q3 ? d00 : d01;
        float k1 = q3 ? d11 : d10, g1 = q3 ? d10 : d11;
        r0 = k0 + __shfl_xor_sync(FULLM, g0, 8);
        r1 = k1 + __shfl_xor_sync(FULLM, g1, 8);
    }
}

__global__ void __launch_bounds__(256, 2)
caps_routing_kernel(const float* __restrict__ x,   // [64, 2048, 16]
                    const float* __restrict__ W,   // [2048, 16, 32, 16]
                    float* __restrict__ out)       // [64, 2048, 32]
{
    const int r = blockIdx.x;
    const int b_base = blockIdx.y << 5;   // 0 or 32
    const int tid = threadIdx.x;
    const int lane = tid & 31;
    const int wid = tid >> 5;    // 0..7
    const int bh = lane >> 4;    // 0/1: which b of the pair this half-warp owns
    const int op = lane & 15;    // o-pair index: o = 2op, 2op+1

    // Wsf[i2][c][op][slot]: slot = 2*(i&1) + (o&1); row (1024 floats) padded to 1028
    __shared__ float  Wsf[8 * 1028];          // 32896 B
    __shared__ float4 Xs[32 * 8];             // [b_loc][i2] = (x_e,x_e,x_o,x_o)  4 KB
    __shared__ float2 Rbuf[8][2][2][16];      // [wid][g][bh][c] = (e,e)          4 KB

    // ---- stage W[r] (32 KB): coalesced LDG.128 + scalar scatter transpose ----
    {
        const float4* Wg4 = reinterpret_cast<const float4*>(W + (size_t)r * 8192);
#pragma unroll
        for (int k = 0; k < 8; k++) {
            int f = tid + (k << 8);          // [c][o][i4]
            float4 v = Wg4[f];
            int c = f >> 7, o = (f >> 2) & 31, i4 = f & 3;
            int base = (c * 16 + (o >> 1)) * 4 + (o & 1);
            float* d0 = &Wsf[(2 * i4) * 1028 + base];
            float* d1 = &Wsf[(2 * i4 + 1) * 1028 + base];
            d0[0] = v.x;                     // i = 4i4+0 -> slot (o&1)
            d0[2] = v.y;                     // i = 4i4+1 -> slot 2+(o&1)
            d1[0] = v.z;                     // i = 4i4+2
            d1[2] = v.w;                     // i = 4i4+3
        }
    }
    // ---- stage x duplicated: Xs[b_loc][i2] = (x[2i2],x[2i2],x[2i2+1],x[2i2+1]) ----
    if (tid < 128) {
        int b_loc = tid >> 2, q = tid & 3;
        const float4* xg = reinterpret_cast<const float4*>(
            x + (size_t)(b_base + b_loc) * 32768 + (size_t)r * 16);
        float4 v = xg[q];
        Xs[b_loc * 8 + 2 * q]     = make_float4(v.x, v.x, v.y, v.y);
        Xs[b_loc * 8 + 2 * q + 1] = make_float4(v.z, v.z, v.w, v.w);
    }
    __syncthreads();

    // ---- u_hat: u[g][c] = (u[b][c][2op], u[b][c][2op+1]), b = b_base+4wid+2g+bh ----
    float2 u[2][16];
#pragma unroll
    for (int g = 0; g < 2; g++)
#pragma unroll
        for (int c = 0; c < 16; c++) u[g][c] = make_float2(0.f, 0.f);

#pragma unroll
    for (int i2 = 0; i2 < 8; i2++) {
        float4 xq0 = Xs[(4 * wid + 0 + bh) * 8 + i2];   // g=0 (2 bcast addrs/half)
        float4 xq1 = Xs[(4 * wid + 2 + bh) * 8 + i2];   // g=1
        const float* wrow = &Wsf[i2 * 1028 + op * 4];
#pragma unroll
        for (int c = 0; c < 16; c++) {
            float4 w4 = *reinterpret_cast<const float4*>(wrow + c * 64);
            float2 wlo = make_float2(w4.x, w4.y);       // (W[2op][2i2], W[2op+1][2i2])
            float2 whi = make_float2(w4.z, w4.w);       // i = 2i2+1
            u[0][c] = ffma2(wlo, make_float2(xq0.x, xq0.y), u[0][c]);
            u[0][c] = ffma2(whi, make_float2(xq0.z, xq0.w), u[0][c]);
            u[1][c] = ffma2(wlo, make_float2(xq1.x, xq1.y), u[1][c]);
            u[1][c] = ffma2(whi, make_float2(xq1.z, xq1.w), u[1][c]);
        }
    }

    // ---- routing: 2 g-chains interleaved; half-warps carry independent b's ----
    const float2* U0 = u[0];
    const float2* U1 = u[1];

    // iter1: s = (1/16) sum_c u[c]
    float2 s0, s1;
    {
        float2 t0[4], t1[4];
#pragma unroll
        for (int k = 0; k < 4; k++) {
            t0[k] = add2(add2(U0[4 * k], U0[4 * k + 1]), add2(U0[4 * k + 2], U0[4 * k + 3]));
            t1[k] = add2(add2(U1[4 * k], U1[4 * k + 1]), add2(U1[4 * k + 2], U1[4 * k + 3]));
        }
        s0 = add2(add2(t0[0], t0[1]), add2(t0[2], t0[3]));
        s1 = add2(add2(t1[0], t1[1]), add2(t1[2], t1[3]));
        const float2 k16 = make_float2(0.0625f, 0.0625f);
        s0 = mul2(s0, k16);
        s1 = mul2(s1, k16);
    }

    squash_g2(s0, s1);                  // s -> v
    float bown0, bown1;                 // logit for c = op (per half-warp's b)
    tr16_g2(U0, U1, s0, s1, op, bown0, bown1);

#pragma unroll
    for (int it = 0; it < 2; it++) {
        // deferred-Z softmax: broadcast unnormalized (e,e); Z summed in quad loop
        float e0 = __expf(bown0);
        float e1 = __expf(bown1);
        __syncwarp();
        Rbuf[wid][0][bh][op] = make_float2(e0, e0);
        Rbuf[wid][1][bh][op] = make_float2(e1, e1);
        __syncwarp();

        const float4* rb0 = reinterpret_cast<const float4*>(&Rbuf[wid][0][bh][0]);
        const float4* rb1 = reinterpret_cast<const float4*>(&Rbuf[wid][1][bh][0]);
        float2 sa0 = make_float2(0.f, 0.f), sb0 = make_float2(0.f, 0.f);
        float2 sa1 = make_float2(0.f, 0.f), sb1 = make_float2(0.f, 0.f);
        float Z0 = 0.f, Z1 = 0.f;
#pragma unroll
        for (int j = 0; j < 8; j++) {
            float4 q0 = rb0[j];          // (e_{2j}, e_{2j}, e_{2j+1}, e_{2j+1})
            float4 q1 = rb1[j];
            sa0 = ffma2(make_float2(q0.x, q0.y), U0[2 * j + 0], sa0);
            sb0 = ffma2(make_float2(q0.z, q0.w), U0[2 * j + 1], sb0);
            sa1 = ffma2(make_float2(q1.x, q1.y), U1[2 * j + 0], sa1);
            sb1 = ffma2(make_float2(q1.z, q1.w), U1[2 * j + 1], sb1);
            Z0 += q0.x; Z0 += q0.z;
            Z1 += q1.x; Z1 += q1.z;
        }
        s0 = mul2(add2(sa0, sb0), pack2(rcp_approx(Z0)));
        s1 = mul2(add2(sa1, sb1), pack2(rcp_approx(Z1)));

        squash_g2(s0, s1);               // s -> v

        if (it == 0) {
            float d0, d1;
            tr16_g2(U0, U1, s0, s1, op, d0, d1);
            bown0 += d0;
            bown1 += d1;
        }
    }

    // ---- write v: out[b][r][2op..2op+1] as STG.64 ----
    {
        const int bg0 = b_base + 4 * wid + 0 + bh;
        const int bg1 = b_base + 4 * wid + 2 + bh;
        *reinterpret_cast<float2*>(out + (size_t)bg0 * 65536 + (size_t)r * 32 + 2 * op) = s0;
        *reinterpret_cast<float2*>(out + (size_t)bg1 * 65536 + (size_t)r * 32 + 2 * op) = s1;
    }
}

extern "C" void kernel_launch(void* const* d_in, const int* in_sizes, int n_in,
                              void* d_out, int out_size) {
    const float* x = (const float*)d_in[0];
    const float* W = (const float*)d_in[1];
    // defensive: x is the smaller input (2,097,152 vs 16,777,216 elements)
    if (n_in >= 2 && in_sizes[0] > in_sizes[1]) {
        const float* t = x; x = W; W = t;
    }
    float* out = (float*)d_out;
    dim3 grid(2048, 2);
    caps_routing_kernel<<<grid, 256>>>(x, W, out);
}